// round 1
// baseline (speedup 1.0000x reference)
#include <cuda_runtime.h>

// Problem constants (fixed by the dataset)
#define BDIM 76
#define NDIM 151
#define KNEI 10
#define HDIM 512
#define FB 5
#define FA 89
#define MN (BDIM * NDIM)          // 11476 nodes
#define LDU2 (HDIM + FB)          // 517
#define LDU1 (2 * HDIM)           // 1024
#define DEPTH 3

// Scratch (static device globals — no allocation allowed)
__device__ float g_A0[MN * HDIM];      // atom features ping
__device__ float g_A1[MN * HDIM];      // atom features pong
__device__ float g_AGG[MN * HDIM];     // gather-sum result / bondc temp
__device__ float g_CONST[MN * HDIM];   // depth-invariant additive term
__device__ float g_Wf[HDIM * HDIM];    // folded W_U1b @ W_U2a

// ---------------------------------------------------------------------------
// Generic tiled fp32 GEMM: C[m,n] = sum_k A[m,k] * B(n,k)  (+ optional 2nd
// A/B pair with same K, + optional bias[n], + optional add-matrix[m,n]).
// B_KN=false: B accessed B[n*ldb + k]  (i.e. C = A @ B^T, both row-contig)
// B_KN=true : B accessed B[k*ldb + n]  (i.e. C = A @ B)
// ---------------------------------------------------------------------------
template <bool B_KN, bool DUAL, bool HAS_BIAS, bool HAS_ADD>
__global__ void gemm_kernel(float* __restrict__ C, int ldc,
                            const float* __restrict__ A0, int lda0,
                            const float* __restrict__ B0, int ldb0,
                            const float* __restrict__ A1, int lda1,
                            const float* __restrict__ B1, int ldb1,
                            const float* __restrict__ bias,
                            const float* __restrict__ addm, int ldadd,
                            int M, int N, int K) {
    constexpr int BM = 64, BN = 64, BK = 16;
    __shared__ float As[BK][BM];
    __shared__ float Bs[BK][BN];

    const int bm = blockIdx.y * BM;
    const int bn = blockIdx.x * BN;
    const int tid = threadIdx.x;          // 256 threads
    const int tx = tid % 16;              // 16x16 thread grid
    const int ty = tid / 16;

    float acc[4][4] = {};

    const int npass = DUAL ? 2 : 1;
    for (int pass = 0; pass < npass; ++pass) {
        const float* A = (DUAL && pass) ? A1 : A0;
        const int lda   = (DUAL && pass) ? lda1 : lda0;
        const float* Bp = (DUAL && pass) ? B1 : B0;
        const int ldb   = (DUAL && pass) ? ldb1 : ldb0;

        for (int k0 = 0; k0 < K; k0 += BK) {
            // Load A tile (BM x BK): 1024 elems / 256 threads = 4 each
            #pragma unroll
            for (int i = tid; i < BM * BK; i += 256) {
                int m = i / BK, kk = i % BK;
                int gm = bm + m, gk = k0 + kk;
                float v = 0.f;
                if (gm < M && gk < K) v = __ldg(&A[(long)gm * lda + gk]);
                As[kk][m] = v;
            }
            // Load B tile (BN x BK)
            #pragma unroll
            for (int i = tid; i < BN * BK; i += 256) {
                int n = i / BK, kk = i % BK;
                int gn = bn + n, gk = k0 + kk;
                float v = 0.f;
                if (gn < N && gk < K)
                    v = B_KN ? __ldg(&Bp[(long)gk * ldb + gn])
                             : __ldg(&Bp[(long)gn * ldb + gk]);
                Bs[kk][n] = v;
            }
            __syncthreads();

            #pragma unroll
            for (int kk = 0; kk < BK; ++kk) {
                float a[4], b[4];
                #pragma unroll
                for (int i = 0; i < 4; ++i) a[i] = As[kk][ty * 4 + i];
                #pragma unroll
                for (int j = 0; j < 4; ++j) b[j] = Bs[kk][tx * 4 + j];
                #pragma unroll
                for (int i = 0; i < 4; ++i)
                    #pragma unroll
                    for (int j = 0; j < 4; ++j) acc[i][j] += a[i] * b[j];
            }
            __syncthreads();
        }
    }

    #pragma unroll
    for (int i = 0; i < 4; ++i) {
        int gm = bm + ty * 4 + i;
        if (gm >= M) continue;
        #pragma unroll
        for (int j = 0; j < 4; ++j) {
            int gn = bn + tx * 4 + j;
            if (gn >= N) continue;
            float v = acc[i][j];
            if (HAS_BIAS) v += __ldg(&bias[gn]);
            if (HAS_ADD) v += __ldg(&addm[(long)gm * ldadd + gn]);
            C[(long)gm * ldc + gn] = v;
        }
    }
}

// ---------------------------------------------------------------------------
// Gather-sum over masked neighbors: AGG[node,h] = sum_{k<num_nbs} A[b, aidx, h]
// One block per node, 256 threads, 2 h-columns per thread.
// ---------------------------------------------------------------------------
__global__ void gather_sum_kernel(const float* __restrict__ A,
                                  const int* __restrict__ aidx,
                                  const int* __restrict__ num_nbs,
                                  float* __restrict__ AGG) {
    const int node = blockIdx.x;               // 0..MN-1
    const int b = node / NDIM;
    const int h = threadIdx.x;                 // 0..255
    const int nn = num_nbs[node];              // in [0, K]
    const float* Abase = A + (long)b * NDIM * HDIM;
    float s0 = 0.f, s1 = 0.f;
    #pragma unroll
    for (int k = 0; k < KNEI; ++k) {
        if (k >= nn) break;                    // mask = (k < num_nbs), prefix
        int idx = __ldg(&aidx[((long)node * KNEI + k) * 2]);
        const float* row = Abase + (long)idx * HDIM;
        s0 += __ldg(&row[h]);
        s1 += __ldg(&row[h + 256]);
    }
    AGG[(long)node * HDIM + h] = s0;
    AGG[(long)node * HDIM + h + 256] = s1;
}

// ---------------------------------------------------------------------------
// Depth-invariant bond path:
//   sbond[f] = sum_{k<nn} input_bond[b, bidx[k], f] ; cnt = nn
//   bondc[node,h] = sum_f sbond[f] * W_U2[h, H+f] + cnt * b_U2[h]
// ---------------------------------------------------------------------------
__global__ void bond_kernel(const float* __restrict__ input_bond,
                            const int* __restrict__ bidx,
                            const int* __restrict__ num_nbs,
                            const float* __restrict__ W_U2,
                            const float* __restrict__ b_U2,
                            float* __restrict__ bondc) {
    const int node = blockIdx.x;
    const int b = node / NDIM;
    __shared__ float sbond[FB];
    __shared__ float scnt;
    const int tid = threadIdx.x;               // 128 threads
    if (tid < FB) {
        const int nn = num_nbs[node];
        float s = 0.f;
        for (int k = 0; k < nn; ++k) {
            int idx = __ldg(&bidx[((long)node * KNEI + k) * 2]);
            s += __ldg(&input_bond[((long)b * NDIM + idx) * FB + tid]);
        }
        sbond[tid] = s;
        if (tid == 0) scnt = (float)num_nbs[node];
    }
    __syncthreads();
    const float c = scnt;
    for (int h = tid; h < HDIM; h += blockDim.x) {
        float v = c * __ldg(&b_U2[h]);
        #pragma unroll
        for (int f = 0; f < FB; ++f)
            v += sbond[f] * __ldg(&W_U2[(long)h * LDU2 + HDIM + f]);
        bondc[(long)node * HDIM + h] = v;
    }
}

// ---------------------------------------------------------------------------
extern "C" void kernel_launch(void* const* d_in, const int* in_sizes, int n_in,
                              void* d_out, int out_size) {
    const float* input_atom = (const float*)d_in[0];   // [B,N,89]
    const float* input_bond = (const float*)d_in[1];   // [B,N,5]
    const int*   atom_nei   = (const int*)d_in[2];     // [B,N,K,2]
    const int*   bond_nei   = (const int*)d_in[3];     // [B,N,K,2]
    const int*   num_nbs    = (const int*)d_in[4];     // [B,N]
    const float* W_atom     = (const float*)d_in[5];   // [512,89]
    const float* W_U2       = (const float*)d_in[6];   // [512,517]
    const float* b_U2       = (const float*)d_in[7];   // [512]
    const float* W_U1       = (const float*)d_in[8];   // [512,1024]
    const float* b_U1       = (const float*)d_in[9];   // [512]
    // d_in[10] (depth) ignored: fixed at 3 by the dataset
    float* out = (float*)d_out;

    float *A0, *A1, *AGG, *CONSTm, *Wf;
    cudaGetSymbolAddress((void**)&A0, g_A0);
    cudaGetSymbolAddress((void**)&A1, g_A1);
    cudaGetSymbolAddress((void**)&AGG, g_AGG);
    cudaGetSymbolAddress((void**)&CONSTm, g_CONST);
    cudaGetSymbolAddress((void**)&Wf, g_Wf);

    const dim3 thr(256);
    const dim3 grid_main((HDIM + 63) / 64, (MN + 63) / 64);   // 8 x 180
    const dim3 grid_sq((HDIM + 63) / 64, (HDIM + 63) / 64);   // 8 x 8

    // 1. Embed: A0 = input_atom @ W_atom^T   [MN,512], K=89
    gemm_kernel<false, false, false, false><<<grid_main, thr>>>(
        A0, HDIM, input_atom, FA, W_atom, FA,
        nullptr, 0, nullptr, 0, nullptr, nullptr, 0, MN, HDIM, FA);

    // 2. Bond precompute -> bondc (stored in AGG scratch)
    bond_kernel<<<MN, 128>>>(input_bond, bond_nei, num_nbs, W_U2, b_U2, AGG);

    // 3. Fold: Wf[i,j] = sum_m W_U1[i, 512+m] * W_U2[m, j]   (B in [K,N] form)
    gemm_kernel<true, false, false, false><<<grid_sq, thr>>>(
        Wf, HDIM, W_U1 + HDIM, LDU1, W_U2, LDU2,
        nullptr, 0, nullptr, 0, nullptr, nullptr, 0, HDIM, HDIM, HDIM);

    // 4. CONST = bondc @ W_U1b^T + b_U1   (W_U1b = W_U1[:, 512:], ldb=1024)
    gemm_kernel<false, false, true, false><<<grid_main, thr>>>(
        CONSTm, HDIM, AGG, HDIM, W_U1 + HDIM, LDU1,
        nullptr, 0, nullptr, 0, b_U1, nullptr, 0, MN, HDIM, HDIM);

    // 5. depth iterations: AGG = gather-sum(A);  A' = A@W_U1a^T + AGG@Wf^T + CONST
    float* src = A0;
    for (int d = 0; d < DEPTH; ++d) {
        gather_sum_kernel<<<MN, 256>>>(src, atom_nei, num_nbs, AGG);
        float* dst = (d == DEPTH - 1) ? out : (src == A0 ? A1 : A0);
        gemm_kernel<false, true, false, true><<<grid_main, thr>>>(
            dst, HDIM, src, HDIM, W_U1, LDU1,
            AGG, HDIM, Wf, HDIM,
            nullptr, CONSTm, HDIM, MN, HDIM, HDIM);
        src = dst;
    }
}

// round 2
// speedup vs baseline: 2.0569x; 2.0569x over previous
#include <cuda_runtime.h>

// Problem constants (fixed by the dataset)
#define BDIM 76
#define NDIM 151
#define KNEI 10
#define HDIM 512
#define FB 5
#define FA 89
#define MN (BDIM * NDIM)          // 11476 nodes
#define LDU2 (HDIM + FB)          // 517
#define LDU1 (2 * HDIM)           // 1024
#define DEPTH 3

// Scratch (static device globals — no allocation allowed)
__device__ float g_A0[MN * HDIM];      // atom features ping
__device__ float g_A1[MN * HDIM];      // atom features pong
__device__ float g_AGG[MN * HDIM];     // gather-sum result / bondc temp
__device__ float g_CONST[MN * HDIM];   // depth-invariant additive term
__device__ float g_Wf[HDIM * HDIM];    // folded W_U1b @ W_U2a

// ---------------------------------------------------------------------------
// 128x128x8 double-buffered SGEMM, 8x8 register microtile, 256 threads.
// C[m,n] = sum_k A[m,k]*B(n,k)  (+optional second A/B pair, +bias, +add).
// B_KN=false: B[n*ldb+k] (C = A@B^T).  B_KN=true: B[k*ldb+n] (C = A@B).
// VECA/VECB: float4 global loads allowed (requires ld %4==0, 16B-aligned base,
// and K%8==0 for the vec operand). N must be a multiple of 128, ldc%4==0.
// ---------------------------------------------------------------------------
template <bool B_KN, bool DUAL, bool HAS_BIAS, bool HAS_ADD, bool VECA, bool VECB>
__global__ __launch_bounds__(256, 2)
void gemm128(float* __restrict__ C, int ldc,
             const float* __restrict__ A0, int lda0,
             const float* __restrict__ B0, int ldb0,
             const float* __restrict__ A1, int lda1,
             const float* __restrict__ B1, int ldb1,
             const float* __restrict__ bias,
             const float* __restrict__ addm, int ldadd,
             int M, int N, int K) {
    constexpr int BM = 128, BN = 128, BK = 8;
    __shared__ float As[2][BK][BM];
    __shared__ float Bs[2][BK][BN];

    const int bm = blockIdx.y * BM;
    const int bn = blockIdx.x * BN;
    const int tid = threadIdx.x;
    const int tx = tid & 15;          // n-dim thread coord
    const int ty = tid >> 4;          // m-dim thread coord

    // Loader coords (A-style: 128 rows x 8 cols, 1 float4 per thread)
    const int arow = tid >> 1;        // 0..127
    const int acol = (tid & 1) * 4;   // 0 or 4
    // B_KN=true loader coords (8 rows x 128 cols)
    const int bkk = tid >> 5;         // 0..7
    const int bkn = (tid & 31) * 4;   // 0..124

    float acc[8][8] = {};
    float aFrag[4], bFrag[4];

    const int npass = DUAL ? 2 : 1;
    for (int pass = 0; pass < npass; ++pass) {
        const float* A  = (DUAL && pass) ? A1 : A0;
        const int lda   = (DUAL && pass) ? lda1 : lda0;
        const float* Bp = (DUAL && pass) ? B1 : B0;
        const int ldb   = (DUAL && pass) ? ldb1 : ldb0;

        // ---- tile loaders (G->regs) ----
        auto loadA = [&](int k0) {
            const int gm = bm + arow;
            const int gk = k0 + acol;
            if (VECA) {
                if (gm < M) {
                    const float4 v = *(const float4*)&A[(size_t)gm * lda + gk];
                    aFrag[0] = v.x; aFrag[1] = v.y; aFrag[2] = v.z; aFrag[3] = v.w;
                } else {
                    aFrag[0] = aFrag[1] = aFrag[2] = aFrag[3] = 0.f;
                }
            } else {
                #pragma unroll
                for (int c = 0; c < 4; ++c)
                    aFrag[c] = (gm < M && gk + c < K)
                               ? __ldg(&A[(size_t)gm * lda + gk + c]) : 0.f;
            }
        };
        auto loadB = [&](int k0) {
            if (!B_KN) {
                const int gn = bn + arow;
                const int gk = k0 + acol;
                if (VECB) {
                    if (gn < N) {
                        const float4 v = *(const float4*)&Bp[(size_t)gn * ldb + gk];
                        bFrag[0] = v.x; bFrag[1] = v.y; bFrag[2] = v.z; bFrag[3] = v.w;
                    } else {
                        bFrag[0] = bFrag[1] = bFrag[2] = bFrag[3] = 0.f;
                    }
                } else {
                    #pragma unroll
                    for (int c = 0; c < 4; ++c)
                        bFrag[c] = (gn < N && gk + c < K)
                                   ? __ldg(&Bp[(size_t)gn * ldb + gk + c]) : 0.f;
                }
            } else {
                const int gk = k0 + bkk;
                const int gn = bn + bkn;
                if (VECB) {
                    if (gk < K && gn < N) {
                        const float4 v = *(const float4*)&Bp[(size_t)gk * ldb + gn];
                        bFrag[0] = v.x; bFrag[1] = v.y; bFrag[2] = v.z; bFrag[3] = v.w;
                    } else {
                        bFrag[0] = bFrag[1] = bFrag[2] = bFrag[3] = 0.f;
                    }
                } else {
                    #pragma unroll
                    for (int c = 0; c < 4; ++c)
                        bFrag[c] = (gk < K && gn + c < N)
                                   ? __ldg(&Bp[(size_t)gk * ldb + gn + c]) : 0.f;
                }
            }
        };
        auto stsTiles = [&](int b) {
            #pragma unroll
            for (int c = 0; c < 4; ++c) As[b][acol + c][arow] = aFrag[c];
            if (!B_KN) {
                #pragma unroll
                for (int c = 0; c < 4; ++c) Bs[b][acol + c][arow] = bFrag[c];
            } else {
                *(float4*)&Bs[b][bkk][bkn] = make_float4(bFrag[0], bFrag[1],
                                                         bFrag[2], bFrag[3]);
            }
        };

        // ---- prologue ----
        loadA(0); loadB(0);
        stsTiles(0);
        __syncthreads();

        int buf = 0;
        for (int k0 = 0; k0 < K; k0 += BK) {
            const bool has_next = (k0 + BK) < K;
            if (has_next) { loadA(k0 + BK); loadB(k0 + BK); }

            #pragma unroll
            for (int kk = 0; kk < BK; ++kk) {
                float a[8], b[8];
                const float4 a0 = *(const float4*)&As[buf][kk][ty * 4];
                const float4 a1 = *(const float4*)&As[buf][kk][ty * 4 + 64];
                const float4 b0 = *(const float4*)&Bs[buf][kk][tx * 4];
                const float4 b1 = *(const float4*)&Bs[buf][kk][tx * 4 + 64];
                a[0]=a0.x; a[1]=a0.y; a[2]=a0.z; a[3]=a0.w;
                a[4]=a1.x; a[5]=a1.y; a[6]=a1.z; a[7]=a1.w;
                b[0]=b0.x; b[1]=b0.y; b[2]=b0.z; b[3]=b0.w;
                b[4]=b1.x; b[5]=b1.y; b[6]=b1.z; b[7]=b1.w;
                #pragma unroll
                for (int i = 0; i < 8; ++i)
                    #pragma unroll
                    for (int j = 0; j < 8; ++j)
                        acc[i][j] += a[i] * b[j];
            }

            if (has_next) stsTiles(buf ^ 1);
            __syncthreads();
            buf ^= 1;
        }
    }

    // ---- epilogue: vectorized stores (all calls have N%128==0, ldc%4==0) ----
    #pragma unroll
    for (int i = 0; i < 8; ++i) {
        const int gm = bm + ((i < 4) ? ty * 4 + i : 64 + ty * 4 + (i - 4));
        if (gm >= M) continue;
        #pragma unroll
        for (int half = 0; half < 2; ++half) {
            const int gn = bn + tx * 4 + half * 64;
            float4 v = make_float4(acc[i][half * 4 + 0], acc[i][half * 4 + 1],
                                   acc[i][half * 4 + 2], acc[i][half * 4 + 3]);
            if (HAS_BIAS) {
                const float4 bb = *(const float4*)&bias[gn];
                v.x += bb.x; v.y += bb.y; v.z += bb.z; v.w += bb.w;
            }
            if (HAS_ADD) {
                const float4 ad = *(const float4*)&addm[(size_t)gm * ldadd + gn];
                v.x += ad.x; v.y += ad.y; v.z += ad.z; v.w += ad.w;
            }
            *(float4*)&C[(size_t)gm * ldc + gn] = v;
        }
    }
}

// ---------------------------------------------------------------------------
// Gather-sum over masked neighbors: AGG[node,h] = sum_{k<num_nbs} A[b, aidx, h]
// ---------------------------------------------------------------------------
__global__ void gather_sum_kernel(const float* __restrict__ A,
                                  const int* __restrict__ aidx,
                                  const int* __restrict__ num_nbs,
                                  float* __restrict__ AGG) {
    const int node = blockIdx.x;               // 0..MN-1
    const int b = node / NDIM;
    const int h = threadIdx.x * 4;             // 128 threads, float4 each
    const int nn = num_nbs[node];              // in [0, K]
    const float* Abase = A + (size_t)b * NDIM * HDIM;
    float4 s = make_float4(0.f, 0.f, 0.f, 0.f);
    #pragma unroll
    for (int k = 0; k < KNEI; ++k) {
        if (k >= nn) break;
        int idx = __ldg(&aidx[((size_t)node * KNEI + k) * 2]);
        const float4 v = *(const float4*)&Abase[(size_t)idx * HDIM + h];
        s.x += v.x; s.y += v.y; s.z += v.z; s.w += v.w;
    }
    *(float4*)&AGG[(size_t)node * HDIM + h] = s;
}

// ---------------------------------------------------------------------------
// Depth-invariant bond path:
//   sbond[f] = sum_{k<nn} input_bond[b, bidx[k], f] ; cnt = nn
//   bondc[node,h] = sum_f sbond[f] * W_U2[h, H+f] + cnt * b_U2[h]
// ---------------------------------------------------------------------------
__global__ void bond_kernel(const float* __restrict__ input_bond,
                            const int* __restrict__ bidx,
                            const int* __restrict__ num_nbs,
                            const float* __restrict__ W_U2,
                            const float* __restrict__ b_U2,
                            float* __restrict__ bondc) {
    const int node = blockIdx.x;
    const int b = node / NDIM;
    __shared__ float sbond[FB];
    __shared__ float scnt;
    const int tid = threadIdx.x;               // 128 threads
    if (tid < FB) {
        const int nn = num_nbs[node];
        float s = 0.f;
        for (int k = 0; k < nn; ++k) {
            int idx = __ldg(&bidx[((size_t)node * KNEI + k) * 2]);
            s += __ldg(&input_bond[((size_t)b * NDIM + idx) * FB + tid]);
        }
        sbond[tid] = s;
        if (tid == 0) scnt = (float)num_nbs[node];
    }
    __syncthreads();
    const float c = scnt;
    for (int h = tid; h < HDIM; h += blockDim.x) {
        float v = c * __ldg(&b_U2[h]);
        #pragma unroll
        for (int f = 0; f < FB; ++f)
            v += sbond[f] * __ldg(&W_U2[(size_t)h * LDU2 + HDIM + f]);
        bondc[(size_t)node * HDIM + h] = v;
    }
}

// ---------------------------------------------------------------------------
extern "C" void kernel_launch(void* const* d_in, const int* in_sizes, int n_in,
                              void* d_out, int out_size) {
    const float* input_atom = (const float*)d_in[0];   // [B,N,89]
    const float* input_bond = (const float*)d_in[1];   // [B,N,5]
    const int*   atom_nei   = (const int*)d_in[2];     // [B,N,K,2]
    const int*   bond_nei   = (const int*)d_in[3];     // [B,N,K,2]
    const int*   num_nbs    = (const int*)d_in[4];     // [B,N]
    const float* W_atom     = (const float*)d_in[5];   // [512,89]
    const float* W_U2       = (const float*)d_in[6];   // [512,517]
    const float* b_U2       = (const float*)d_in[7];   // [512]
    const float* W_U1       = (const float*)d_in[8];   // [512,1024]
    const float* b_U1       = (const float*)d_in[9];   // [512]
    float* out = (float*)d_out;

    float *A0, *A1, *AGG, *CONSTm, *Wf;
    cudaGetSymbolAddress((void**)&A0, g_A0);
    cudaGetSymbolAddress((void**)&A1, g_A1);
    cudaGetSymbolAddress((void**)&AGG, g_AGG);
    cudaGetSymbolAddress((void**)&CONSTm, g_CONST);
    cudaGetSymbolAddress((void**)&Wf, g_Wf);

    const dim3 thr(256);
    const dim3 grid_main(HDIM / 128, (MN + 127) / 128);   // 4 x 90
    const dim3 grid_sq(HDIM / 128, HDIM / 128);           // 4 x 4

    // 1. Embed: A0 = input_atom @ W_atom^T   [MN,512], K=89 (scalar loads)
    gemm128<false, false, false, false, false, false><<<grid_main, thr>>>(
        A0, HDIM, input_atom, FA, W_atom, FA,
        nullptr, 0, nullptr, 0, nullptr, nullptr, 0, MN, HDIM, FA);

    // 2. Bond precompute -> bondc (stored in AGG scratch)
    bond_kernel<<<MN, 128>>>(input_bond, bond_nei, num_nbs, W_U2, b_U2, AGG);

    // 3. Fold: Wf = W_U1b @ W_U2a   (B in [K,N] form, ldb=517 -> scalar B)
    gemm128<true, false, false, false, true, false><<<grid_sq, thr>>>(
        Wf, HDIM, W_U1 + HDIM, LDU1, W_U2, LDU2,
        nullptr, 0, nullptr, 0, nullptr, nullptr, 0, HDIM, HDIM, HDIM);

    // 4. CONST = bondc @ W_U1b^T + b_U1
    gemm128<false, false, true, false, true, true><<<grid_main, thr>>>(
        CONSTm, HDIM, AGG, HDIM, W_U1 + HDIM, LDU1,
        nullptr, 0, nullptr, 0, b_U1, nullptr, 0, MN, HDIM, HDIM);

    // 5. depth iterations: AGG = gather-sum(A);  A' = A@W_U1a^T + AGG@Wf^T + CONST
    float* src = A0;
    for (int d = 0; d < DEPTH; ++d) {
        gather_sum_kernel<<<MN, 128>>>(src, atom_nei, num_nbs, AGG);
        float* dst = (d == DEPTH - 1) ? out : (src == A0 ? A1 : A0);
        gemm128<false, true, false, true, true, true><<<grid_main, thr>>>(
            dst, HDIM, src, HDIM, W_U1, LDU1,
            AGG, HDIM, Wf, HDIM,
            nullptr, CONSTm, HDIM, MN, HDIM, HDIM);
        src = dst;
    }
}

// round 4
// speedup vs baseline: 4.5015x; 2.1885x over previous
#include <cuda_runtime.h>
#include <cuda_bf16.h>
#include <cstdint>

// Problem constants (fixed by the dataset)
#define BDIM 76
#define NDIM 151
#define KNEI 10
#define HDIM 512
#define FB 5
#define FA 89
#define MN (BDIM * NDIM)          // 11476 nodes
#define LDU2 (HDIM + FB)          // 517
#define LDU1 (2 * HDIM)           // 1024
#define DEPTH 3

// ---------------- static device scratch (no allocation allowed) -------------
__device__ __align__(128) float g_A0[MN * HDIM];
__device__ __align__(128) float g_A1[MN * HDIM];
__device__ __align__(128) float g_AGG[MN * HDIM];
__device__ __align__(128) float g_CONST[MN * HDIM];
__device__ __align__(128) float g_Wf[HDIM * HDIM];
__device__ __align__(128) float g_Wt[HDIM * HDIM];     // W_U2a transposed
__device__ float g_zero512[HDIM];                      // zero bias

__device__ __align__(128) __nv_bfloat16 g_Ahi[MN * HDIM], g_Alo[MN * HDIM];
__device__ __align__(128) __nv_bfloat16 g_GGhi[MN * HDIM], g_GGlo[MN * HDIM];
__device__ __align__(128) __nv_bfloat16 g_BChi[MN * HDIM], g_BClo[MN * HDIM];
__device__ __align__(128) __nv_bfloat16 g_Wahi[HDIM * HDIM], g_Walo[HDIM * HDIM];
__device__ __align__(128) __nv_bfloat16 g_Wbhi[HDIM * HDIM], g_Wblo[HDIM * HDIM];
__device__ __align__(128) __nv_bfloat16 g_Wfhi[HDIM * HDIM], g_Wflo[HDIM * HDIM];
__device__ __align__(128) __nv_bfloat16 g_Wthi[HDIM * HDIM], g_Wtlo[HDIM * HDIM];

// ======================= PTX helpers (sm_80-safe only) ======================
__device__ __forceinline__ uint32_t smem_u32(const void* p) {
    uint32_t a;
    asm("{ .reg .u64 t; cvta.to.shared.u64 t, %1; cvt.u32.u64 %0, t; }"
        : "=r"(a) : "l"(p));
    return a;
}
__device__ __forceinline__ void cp_async16(uint32_t dst, const void* src, int sz) {
    asm volatile("cp.async.cg.shared.global [%0], [%1], 16, %2;"
                 :: "r"(dst), "l"(src), "r"(sz) : "memory");
}
__device__ __forceinline__ void ldsm_x4(uint32_t addr, uint32_t* r) {
    asm volatile("ldmatrix.sync.aligned.m8n8.x4.shared.b16 {%0,%1,%2,%3}, [%4];"
                 : "=r"(r[0]), "=r"(r[1]), "=r"(r[2]), "=r"(r[3]) : "r"(addr));
}
__device__ __forceinline__ void mma_bf16(float* c, const uint32_t* a,
                                         uint32_t b0, uint32_t b1) {
    asm volatile(
        "mma.sync.aligned.m16n8k16.row.col.f32.bf16.bf16.f32 "
        "{%0,%1,%2,%3}, {%4,%5,%6,%7}, {%8,%9}, {%0,%1,%2,%3};"
        : "+f"(c[0]), "+f"(c[1]), "+f"(c[2]), "+f"(c[3])
        : "r"(a[0]), "r"(a[1]), "r"(a[2]), "r"(a[3]), "r"(b0), "r"(b1));
}

// ======================= bf16 mma.sync GEMM =================================
// C[M, 512] = sum over pairs of A_p[M,512](bf16) @ B_p[512,512](bf16, [n][k])^T
// (+ add matrix [M,512] or bias [512]).  BM=BN=128, BK=64, 3-stage cp.async.
// 256 threads = 8 warps in 4(m) x 2(n); warp tile 32x64.
#define MMA_STAGES 3
#define STAGE_BYTES 32768        // A 16KB + B 16KB
#define SMEM_MMA (MMA_STAGES * STAGE_BYTES)

struct GemmArgs { const __nv_bfloat16* a[6]; const __nv_bfloat16* b[6]; };

template <bool HAS_ADD>
__global__ __launch_bounds__(256, 2)
void mma_gemm(const GemmArgs args, int npairs,
              float* __restrict__ C, const float* __restrict__ add_or_bias,
              int M) {
    extern __shared__ __align__(128) char smem[];
    const uint32_t sbase = smem_u32(smem);
    const int tid = threadIdx.x, wid = tid >> 5, lane = tid & 31;
    const int bm = blockIdx.y * 128, bn = blockIdx.x * 128;
    const int wm = (wid & 3) * 32;     // warp m offset in tile
    const int wn = (wid >> 2) * 64;    // warp n offset in tile

    float acc[2][8][4] = {};

    // ---- stage loader: 256 thr x 16B x 4 iters per operand ----
    const int lrow0 = tid >> 3;        // 0..31
    const int lch = tid & 7;           // 16B chunk within 128B row
    auto load_stage = [&](int g, int s) {
        const int p = g >> 3, kc = g & 7;
        const __nv_bfloat16* Ag = args.a[p];
        const __nv_bfloat16* Bg = args.b[p];
        const uint32_t sa = sbase + s * STAGE_BYTES;
        const uint32_t sb = sa + 16384;
        #pragma unroll
        for (int it = 0; it < 4; ++it) {
            const int row = lrow0 + it * 32;
            const uint32_t soff = row * 128 + ((lch ^ (row & 7)) << 4);
            const long gmr = bm + row;
            cp_async16(sa + soff, Ag + gmr * 512 + kc * 64 + lch * 8,
                       (gmr < M) ? 16 : 0);
            cp_async16(sb + soff, Bg + (long)(bn + row) * 512 + kc * 64 + lch * 8,
                       16);
        }
        asm volatile("cp.async.commit_group;" ::: "memory");
    };

    // ---- compute one 64-K stage ----
    auto compute_stage = [&](int s) {
        const uint32_t sa = sbase + s * STAGE_BYTES;
        const uint32_t sb = sa + 16384;
        #pragma unroll
        for (int ks = 0; ks < 4; ++ks) {
            uint32_t ra[2][4];
            #pragma unroll
            for (int mb = 0; mb < 2; ++mb) {
                const int row = wm + mb * 16 + (lane & 15);
                const int ch = ks * 2 + (lane >> 4);
                ldsm_x4(sa + row * 128 + ((ch ^ (row & 7)) << 4), ra[mb]);
            }
            uint32_t rb[4][4];
            #pragma unroll
            for (int nb = 0; nb < 4; ++nb) {
                const int row = wn + nb * 16 + (lane & 15);
                const int ch = ks * 2 + (lane >> 4);
                ldsm_x4(sb + row * 128 + ((ch ^ (row & 7)) << 4), rb[nb]);
            }
            #pragma unroll
            for (int mb = 0; mb < 2; ++mb)
                #pragma unroll
                for (int nb = 0; nb < 4; ++nb) {
                    mma_bf16(acc[mb][nb * 2],     ra[mb], rb[nb][0], rb[nb][2]);
                    mma_bf16(acc[mb][nb * 2 + 1], ra[mb], rb[nb][1], rb[nb][3]);
                }
        }
    };

    const int NG = npairs * 8;         // 64-K chunks total
    load_stage(0, 0);
    if (NG > 1) load_stage(1, 1);
    for (int g = 0; g < NG; ++g) {
        if (g == NG - 1)
            asm volatile("cp.async.wait_group 0;" ::: "memory");
        else
            asm volatile("cp.async.wait_group 1;" ::: "memory");
        __syncthreads();
        compute_stage(g % MMA_STAGES);
        __syncthreads();
        if (g + 2 < NG) load_stage(g + 2, (g + 2) % MMA_STAGES);
    }

    // ---- epilogue ----
    #pragma unroll
    for (int mb = 0; mb < 2; ++mb)
        #pragma unroll
        for (int nb = 0; nb < 8; ++nb) {
            const int gn = bn + wn + nb * 8 + (lane & 3) * 2;
            #pragma unroll
            for (int h = 0; h < 2; ++h) {
                const int gm = bm + wm + mb * 16 + (lane >> 2) + h * 8;
                if (gm < M) {
                    float2 v = make_float2(acc[mb][nb][h * 2],
                                           acc[mb][nb][h * 2 + 1]);
                    const float* ap = HAS_ADD
                        ? add_or_bias + (long)gm * 512 + gn
                        : add_or_bias + gn;
                    const float2 av = *(const float2*)ap;
                    v.x += av.x; v.y += av.y;
                    *(float2*)&C[(long)gm * 512 + gn] = v;
                }
            }
        }
}

// ======================= fp32 SGEMM (embed only, K=89) ======================
__global__ __launch_bounds__(256, 2)
void embed_gemm(float* __restrict__ C,
                const float* __restrict__ A,       // [MN, 89]
                const float* __restrict__ Bp) {    // [512, 89]
    constexpr int BM = 128, BN = 128, BK = 8;
    __shared__ float As[2][BK][BM];
    __shared__ float Bs[2][BK][BN];
    const int bm = blockIdx.y * BM, bn = blockIdx.x * BN;
    const int tid = threadIdx.x;
    const int tx = tid & 15, ty = tid >> 4;
    const int arow = tid >> 1, acol = (tid & 1) * 4;
    const int M = MN, N = HDIM, K = FA;

    float acc[8][8] = {};
    float aFrag[4], bFrag[4];
    auto loadA = [&](int k0) {
        const int gm = bm + arow, gk = k0 + acol;
        #pragma unroll
        for (int c = 0; c < 4; ++c)
            aFrag[c] = (gm < M && gk + c < K)
                       ? __ldg(&A[(size_t)gm * K + gk + c]) : 0.f;
    };
    auto loadB = [&](int k0) {
        const int gn = bn + arow, gk = k0 + acol;
        #pragma unroll
        for (int c = 0; c < 4; ++c)
            bFrag[c] = (gn < N && gk + c < K)
                       ? __ldg(&Bp[(size_t)gn * K + gk + c]) : 0.f;
    };
    auto sts = [&](int b) {
        #pragma unroll
        for (int c = 0; c < 4; ++c) {
            As[b][acol + c][arow] = aFrag[c];
            Bs[b][acol + c][arow] = bFrag[c];
        }
    };
    loadA(0); loadB(0); sts(0);
    __syncthreads();
    int buf = 0;
    for (int k0 = 0; k0 < K; k0 += BK) {
        const bool nxt = (k0 + BK) < K;
        if (nxt) { loadA(k0 + BK); loadB(k0 + BK); }
        #pragma unroll
        for (int kk = 0; kk < BK; ++kk) {
            float a[8], b[8];
            const float4 a0 = *(const float4*)&As[buf][kk][ty * 4];
            const float4 a1 = *(const float4*)&As[buf][kk][ty * 4 + 64];
            const float4 b0 = *(const float4*)&Bs[buf][kk][tx * 4];
            const float4 b1 = *(const float4*)&Bs[buf][kk][tx * 4 + 64];
            a[0]=a0.x; a[1]=a0.y; a[2]=a0.z; a[3]=a0.w;
            a[4]=a1.x; a[5]=a1.y; a[6]=a1.z; a[7]=a1.w;
            b[0]=b0.x; b[1]=b0.y; b[2]=b0.z; b[3]=b0.w;
            b[4]=b1.x; b[5]=b1.y; b[6]=b1.z; b[7]=b1.w;
            #pragma unroll
            for (int i = 0; i < 8; ++i)
                #pragma unroll
                for (int j = 0; j < 8; ++j) acc[i][j] += a[i] * b[j];
        }
        if (nxt) sts(buf ^ 1);
        __syncthreads();
        buf ^= 1;
    }
    #pragma unroll
    for (int i = 0; i < 8; ++i) {
        const int gm = bm + ((i < 4) ? ty * 4 + i : 64 + ty * 4 + (i - 4));
        if (gm >= M) continue;
        #pragma unroll
        for (int half = 0; half < 2; ++half) {
            const int gn = bn + tx * 4 + half * 64;
            *(float4*)&C[(size_t)gm * N + gn] =
                make_float4(acc[i][half*4+0], acc[i][half*4+1],
                            acc[i][half*4+2], acc[i][half*4+3]);
        }
    }
}

// ======================= small kernels ======================================
__global__ void gather_sum_kernel(const float* __restrict__ A,
                                  const int* __restrict__ aidx,
                                  const int* __restrict__ num_nbs,
                                  float* __restrict__ AGG) {
    const int node = blockIdx.x;
    const int b = node / NDIM;
    const int h = threadIdx.x * 4;
    const int nn = num_nbs[node];
    const float* Abase = A + (size_t)b * NDIM * HDIM;
    float4 s = make_float4(0.f, 0.f, 0.f, 0.f);
    #pragma unroll
    for (int k = 0; k < KNEI; ++k) {
        if (k >= nn) break;
        int idx = __ldg(&aidx[((size_t)node * KNEI + k) * 2]);
        const float4 v = *(const float4*)&Abase[(size_t)idx * HDIM + h];
        s.x += v.x; s.y += v.y; s.z += v.z; s.w += v.w;
    }
    *(float4*)&AGG[(size_t)node * HDIM + h] = s;
}

__global__ void bond_kernel(const float* __restrict__ input_bond,
                            const int* __restrict__ bidx,
                            const int* __restrict__ num_nbs,
                            const float* __restrict__ W_U2,
                            const float* __restrict__ b_U2,
                            float* __restrict__ bondc) {
    const int node = blockIdx.x;
    const int b = node / NDIM;
    __shared__ float sbond[FB];
    __shared__ float scnt;
    const int tid = threadIdx.x;
    if (tid < FB) {
        const int nn = num_nbs[node];
        float s = 0.f;
        for (int k = 0; k < nn; ++k) {
            int idx = __ldg(&bidx[((size_t)node * KNEI + k) * 2]);
            s += __ldg(&input_bond[((size_t)b * NDIM + idx) * FB + tid]);
        }
        sbond[tid] = s;
        if (tid == 0) scnt = (float)num_nbs[node];
    }
    __syncthreads();
    const float c = scnt;
    for (int h = tid; h < HDIM; h += blockDim.x) {
        float v = c * __ldg(&b_U2[h]);
        #pragma unroll
        for (int f = 0; f < FB; ++f)
            v += sbond[f] * __ldg(&W_U2[(size_t)h * LDU2 + HDIM + f]);
        bondc[(size_t)node * HDIM + h] = v;
    }
}

// transpose W_U2[:, 0:512] (ld=517) -> Wt[512][512]: Wt[j][m] = W_U2[m][j]
__global__ void transpose_kernel(const float* __restrict__ W,
                                 float* __restrict__ T) {
    __shared__ float t[32][33];
    const int bx = blockIdx.x * 32, by = blockIdx.y * 32;
    const int x = threadIdx.x, y = threadIdx.y;    // 32 x 8
    #pragma unroll
    for (int i = 0; i < 32; i += 8)
        t[y + i][x] = __ldg(&W[(size_t)(by + y + i) * LDU2 + bx + x]);
    __syncthreads();
    #pragma unroll
    for (int i = 0; i < 32; i += 8)
        T[(size_t)(bx + y + i) * HDIM + by + x] = t[x][y + i];
}

// hi/lo bf16 split, contiguous fp32 input (n4 = count/4)
__global__ void split_kernel(const float* __restrict__ x,
                             __nv_bfloat16* __restrict__ hi,
                             __nv_bfloat16* __restrict__ lo, int n4) {
    const int i = blockIdx.x * blockDim.x + threadIdx.x;
    if (i >= n4) return;
    const float4 v = ((const float4*)x)[i];
    const __nv_bfloat16 hx = __float2bfloat16_rn(v.x);
    const __nv_bfloat16 hy = __float2bfloat16_rn(v.y);
    const __nv_bfloat16 hz = __float2bfloat16_rn(v.z);
    const __nv_bfloat16 hw = __float2bfloat16_rn(v.w);
    __nv_bfloat162* H = (__nv_bfloat162*)hi;
    __nv_bfloat162* L = (__nv_bfloat162*)lo;
    H[2 * i]     = __nv_bfloat162(hx, hy);
    H[2 * i + 1] = __nv_bfloat162(hz, hw);
    L[2 * i]     = __nv_bfloat162(
        __float2bfloat16_rn(v.x - __bfloat162float(hx)),
        __float2bfloat16_rn(v.y - __bfloat162float(hy)));
    L[2 * i + 1] = __nv_bfloat162(
        __float2bfloat16_rn(v.z - __bfloat162float(hz)),
        __float2bfloat16_rn(v.w - __bfloat162float(hw)));
}

// strided weight split: out[n*512 + k] = W[n*ldw + koff + k]
__global__ void split_w_kernel(const float* __restrict__ W, int ldw, int koff,
                               __nv_bfloat16* __restrict__ hi,
                               __nv_bfloat16* __restrict__ lo) {
    const int idx = blockIdx.x * blockDim.x + threadIdx.x;
    if (idx >= HDIM * HDIM) return;
    const int n = idx >> 9, k = idx & 511;
    const float v = __ldg(&W[(size_t)n * ldw + koff + k]);
    const __nv_bfloat16 h = __float2bfloat16_rn(v);
    hi[idx] = h;
    lo[idx] = __float2bfloat16_rn(v - __bfloat162float(h));
}

// ======================= host ===============================================
extern "C" void kernel_launch(void* const* d_in, const int* in_sizes, int n_in,
                              void* d_out, int out_size) {
    const float* input_atom = (const float*)d_in[0];
    const float* input_bond = (const float*)d_in[1];
    const int*   atom_nei   = (const int*)d_in[2];
    const int*   bond_nei   = (const int*)d_in[3];
    const int*   num_nbs    = (const int*)d_in[4];
    const float* W_atom     = (const float*)d_in[5];
    const float* W_U2       = (const float*)d_in[6];
    const float* b_U2       = (const float*)d_in[7];
    const float* W_U1       = (const float*)d_in[8];
    const float* b_U1       = (const float*)d_in[9];
    float* out = (float*)d_out;

    float *A0, *A1, *AGG, *CONSTm, *Wf, *Wt, *zero512;
    cudaGetSymbolAddress((void**)&A0, g_A0);
    cudaGetSymbolAddress((void**)&A1, g_A1);
    cudaGetSymbolAddress((void**)&AGG, g_AGG);
    cudaGetSymbolAddress((void**)&CONSTm, g_CONST);
    cudaGetSymbolAddress((void**)&Wf, g_Wf);
    cudaGetSymbolAddress((void**)&Wt, g_Wt);
    cudaGetSymbolAddress((void**)&zero512, g_zero512);
    __nv_bfloat16 *Ahi, *Alo, *GGhi, *GGlo, *BChi, *BClo;
    __nv_bfloat16 *Wahi, *Walo, *Wbhi, *Wblo, *Wfhi, *Wflo, *Wthi, *Wtlo;
    cudaGetSymbolAddress((void**)&Ahi, g_Ahi);   cudaGetSymbolAddress((void**)&Alo, g_Alo);
    cudaGetSymbolAddress((void**)&GGhi, g_GGhi); cudaGetSymbolAddress((void**)&GGlo, g_GGlo);
    cudaGetSymbolAddress((void**)&BChi, g_BChi); cudaGetSymbolAddress((void**)&BClo, g_BClo);
    cudaGetSymbolAddress((void**)&Wahi, g_Wahi); cudaGetSymbolAddress((void**)&Walo, g_Walo);
    cudaGetSymbolAddress((void**)&Wbhi, g_Wbhi); cudaGetSymbolAddress((void**)&Wblo, g_Wblo);
    cudaGetSymbolAddress((void**)&Wfhi, g_Wfhi); cudaGetSymbolAddress((void**)&Wflo, g_Wflo);
    cudaGetSymbolAddress((void**)&Wthi, g_Wthi); cudaGetSymbolAddress((void**)&Wtlo, g_Wtlo);

    cudaFuncSetAttribute(mma_gemm<true>,
                         cudaFuncAttributeMaxDynamicSharedMemorySize, SMEM_MMA);
    cudaFuncSetAttribute(mma_gemm<false>,
                         cudaFuncAttributeMaxDynamicSharedMemorySize, SMEM_MMA);

    const dim3 thr(256);
    const dim3 grid_main(HDIM / 128, (MN + 127) / 128);   // 4 x 90
    const dim3 grid_sq(HDIM / 128, HDIM / 128);           // 4 x 4
    const int NSPLIT4 = MN * HDIM / 4;
    const int wblocks = (HDIM * HDIM + 255) / 256;

    // 1. Embed: A0 = input_atom @ W_atom^T  (fp32, K=89)
    embed_gemm<<<grid_main, thr>>>(A0, input_atom, W_atom);

    // 2. Bond precompute -> bondc (fp32, stored in AGG)
    bond_kernel<<<MN, 128>>>(input_bond, bond_nei, num_nbs, W_U2, b_U2, AGG);

    // 3. Transpose W_U2a, split all weight operands to bf16 hi/lo
    transpose_kernel<<<dim3(16, 16), dim3(32, 8)>>>(W_U2, Wt);
    split_w_kernel<<<wblocks, 256>>>(W_U1, LDU1, 0, Wahi, Walo);
    split_w_kernel<<<wblocks, 256>>>(W_U1, LDU1, HDIM, Wbhi, Wblo);
    split_kernel<<<(HDIM * HDIM / 4 + 255) / 256, 256>>>(Wt, Wthi, Wtlo,
                                                         HDIM * HDIM / 4);
    split_kernel<<<(NSPLIT4 + 255) / 256, 256>>>(AGG, BChi, BClo, NSPLIT4);

    // 4. Fold: Wf = W_U1b @ W_U2a  (bf16x3 mma; B operand = Wt[n=j][k=m])
    {
        GemmArgs p{};
        p.a[0] = Wbhi; p.a[1] = Wblo; p.a[2] = Wbhi;
        p.b[0] = Wthi; p.b[1] = Wthi; p.b[2] = Wtlo;
        mma_gemm<false><<<grid_sq, thr, SMEM_MMA>>>(p, 3, Wf, zero512, HDIM);
    }
    split_kernel<<<(HDIM * HDIM / 4 + 255) / 256, 256>>>(Wf, Wfhi, Wflo,
                                                         HDIM * HDIM / 4);

    // 5. CONST = bondc @ W_U1b^T + b_U1  (bf16x3 mma)
    {
        GemmArgs p{};
        p.a[0] = BChi; p.a[1] = BClo; p.a[2] = BChi;
        p.b[0] = Wbhi; p.b[1] = Wbhi; p.b[2] = Wblo;
        mma_gemm<false><<<grid_main, thr, SMEM_MMA>>>(p, 3, CONSTm, b_U1, MN);
    }

    // 6. depth iterations: AGG = gather(A); A' = A@W_U1a^T + AGG@Wf^T + CONST
    GemmArgs pd{};
    pd.a[0] = Ahi;  pd.a[1] = Alo;  pd.a[2] = Ahi;
    pd.b[0] = Wahi; pd.b[1] = Wahi; pd.b[2] = Walo;
    pd.a[3] = GGhi; pd.a[4] = GGlo; pd.a[5] = GGhi;
    pd.b[3] = Wfhi; pd.b[4] = Wfhi; pd.b[5] = Wflo;

    float* src = A0;
    for (int d = 0; d < DEPTH; ++d) {
        gather_sum_kernel<<<MN, 128>>>(src, atom_nei, num_nbs, AGG);
        split_kernel<<<(NSPLIT4 + 255) / 256, 256>>>(src, Ahi, Alo, NSPLIT4);
        split_kernel<<<(NSPLIT4 + 255) / 256, 256>>>(AGG, GGhi, GGlo, NSPLIT4);
        float* dst = (d == DEPTH - 1) ? out : (src == A0 ? A1 : A0);
        mma_gemm<true><<<grid_main, thr, SMEM_MMA>>>(pd, 6, dst, CONSTm, MN);
        src = dst;
    }
}

// round 5
// speedup vs baseline: 4.8025x; 1.0669x over previous
#include <cuda_runtime.h>
#include <cuda_bf16.h>
#include <cstdint>

// Problem constants (fixed by the dataset)
#define BDIM 76
#define NDIM 151
#define KNEI 10
#define HDIM 512
#define FB 5
#define FA 89
#define FAP 128                   // padded embed K
#define MN (BDIM * NDIM)          // 11476 nodes
#define LDU2 (HDIM + FB)          // 517
#define LDU1 (2 * HDIM)           // 1024
#define DEPTH 3

// ---------------- static device scratch (no allocation allowed) -------------
__device__ __align__(128) float g_CONST[MN * HDIM];
__device__ __align__(128) float g_Wt[HDIM * HDIM];     // W_U2a transposed
__device__ float g_zero512[HDIM];                      // zero bias

// ping-pong feature buffers (bf16 hi/lo)
__device__ __align__(128) __nv_bfloat16 g_Ahi0[MN * HDIM], g_Alo0[MN * HDIM];
__device__ __align__(128) __nv_bfloat16 g_Ahi1[MN * HDIM], g_Alo1[MN * HDIM];
__device__ __align__(128) __nv_bfloat16 g_GGhi[MN * HDIM], g_GGlo[MN * HDIM];
__device__ __align__(128) __nv_bfloat16 g_BChi[MN * HDIM], g_BClo[MN * HDIM];
__device__ __align__(128) __nv_bfloat16 g_Wahi[HDIM * HDIM], g_Walo[HDIM * HDIM];
__device__ __align__(128) __nv_bfloat16 g_Wbhi[HDIM * HDIM], g_Wblo[HDIM * HDIM];
__device__ __align__(128) __nv_bfloat16 g_Wfhi[HDIM * HDIM], g_Wflo[HDIM * HDIM];
__device__ __align__(128) __nv_bfloat16 g_Wthi[HDIM * HDIM], g_Wtlo[HDIM * HDIM];
// padded embed operands
__device__ __align__(128) __nv_bfloat16 g_Pahi[MN * FAP], g_Palo[MN * FAP];
__device__ __align__(128) __nv_bfloat16 g_PWhi[HDIM * FAP], g_PWlo[HDIM * FAP];

// ======================= PTX helpers (sm_80-safe only) ======================
__device__ __forceinline__ uint32_t smem_u32(const void* p) {
    uint32_t a;
    asm("{ .reg .u64 t; cvta.to.shared.u64 t, %1; cvt.u32.u64 %0, t; }"
        : "=r"(a) : "l"(p));
    return a;
}
__device__ __forceinline__ void cp_async16(uint32_t dst, const void* src, int sz) {
    asm volatile("cp.async.cg.shared.global [%0], [%1], 16, %2;"
                 :: "r"(dst), "l"(src), "r"(sz) : "memory");
}
__device__ __forceinline__ void ldsm_x4(uint32_t addr, uint32_t* r) {
    asm volatile("ldmatrix.sync.aligned.m8n8.x4.shared.b16 {%0,%1,%2,%3}, [%4];"
                 : "=r"(r[0]), "=r"(r[1]), "=r"(r[2]), "=r"(r[3]) : "r"(addr));
}
__device__ __forceinline__ void mma_bf16(float* c, const uint32_t* a,
                                         uint32_t b0, uint32_t b1) {
    asm volatile(
        "mma.sync.aligned.m16n8k16.row.col.f32.bf16.bf16.f32 "
        "{%0,%1,%2,%3}, {%4,%5,%6,%7}, {%8,%9}, {%0,%1,%2,%3};"
        : "+f"(c[0]), "+f"(c[1]), "+f"(c[2]), "+f"(c[3])
        : "r"(a[0]), "r"(a[1]), "r"(a[2]), "r"(a[3]), "r"(b0), "r"(b1));
}
__device__ __forceinline__ __nv_bfloat162 split_hi2(float x, float y,
                                                    __nv_bfloat162& lo2) {
    const __nv_bfloat16 hx = __float2bfloat16_rn(x);
    const __nv_bfloat16 hy = __float2bfloat16_rn(y);
    lo2 = __nv_bfloat162(__float2bfloat16_rn(x - __bfloat162float(hx)),
                         __float2bfloat16_rn(y - __bfloat162float(hy)));
    return __nv_bfloat162(hx, hy);
}

// ======================= bf16 mma.sync GEMM =================================
// C[M, 512] = sum over pairs of A_p[M,LDA](bf16) @ B_p[512,LDA](bf16)^T
// (+ add matrix [M,512] or bias [512]).  BM=BN=128, BK=64, 3-stage cp.async.
// 256 threads = 8 warps in 4(m) x 2(n); warp tile 32x64.
// KCPP = 64-K chunks per pair (LDA/64).  SPLIT: write bf16 hi/lo outputs.
#define MMA_STAGES 3
#define STAGE_BYTES 32768        // A 16KB + B 16KB
#define SMEM_MMA (MMA_STAGES * STAGE_BYTES)

struct GemmArgs { const __nv_bfloat16* a[6]; const __nv_bfloat16* b[6]; };

template <int KCPP, int LDA, bool ADDM, bool SPLIT>
__global__ __launch_bounds__(256, 2)
void mma_gemm(const GemmArgs args, int npairs,
              float* __restrict__ C,
              __nv_bfloat16* __restrict__ Chi, __nv_bfloat16* __restrict__ Clo,
              const float* __restrict__ add_or_bias, int M) {
    extern __shared__ __align__(128) char smem[];
    const uint32_t sbase = smem_u32(smem);
    const int tid = threadIdx.x, wid = tid >> 5, lane = tid & 31;
    const int bm = blockIdx.y * 128, bn = blockIdx.x * 128;
    const int wm = (wid & 3) * 32;     // warp m offset in tile
    const int wn = (wid >> 2) * 64;    // warp n offset in tile

    float acc[2][8][4] = {};

    const int lrow0 = tid >> 3;        // 0..31
    const int lch = tid & 7;           // 16B chunk within 128B row
    auto load_stage = [&](int g, int s) {
        const int p = g / KCPP, kc = g % KCPP;
        const __nv_bfloat16* Ag = args.a[p];
        const __nv_bfloat16* Bg = args.b[p];
        const uint32_t sa = sbase + s * STAGE_BYTES;
        const uint32_t sb = sa + 16384;
        #pragma unroll
        for (int it = 0; it < 4; ++it) {
            const int row = lrow0 + it * 32;
            const uint32_t soff = row * 128 + ((lch ^ (row & 7)) << 4);
            const long gmr = bm + row;
            cp_async16(sa + soff, Ag + gmr * LDA + kc * 64 + lch * 8,
                       (gmr < M) ? 16 : 0);
            cp_async16(sb + soff, Bg + (long)(bn + row) * LDA + kc * 64 + lch * 8,
                       16);
        }
        asm volatile("cp.async.commit_group;" ::: "memory");
    };

    auto compute_stage = [&](int s) {
        const uint32_t sa = sbase + s * STAGE_BYTES;
        const uint32_t sb = sa + 16384;
        #pragma unroll
        for (int ks = 0; ks < 4; ++ks) {
            uint32_t ra[2][4];
            #pragma unroll
            for (int mb = 0; mb < 2; ++mb) {
                const int row = wm + mb * 16 + (lane & 15);
                const int ch = ks * 2 + (lane >> 4);
                ldsm_x4(sa + row * 128 + ((ch ^ (row & 7)) << 4), ra[mb]);
            }
            uint32_t rb[4][4];
            #pragma unroll
            for (int nb = 0; nb < 4; ++nb) {
                const int row = wn + nb * 16 + (lane & 15);
                const int ch = ks * 2 + (lane >> 4);
                ldsm_x4(sb + row * 128 + ((ch ^ (row & 7)) << 4), rb[nb]);
            }
            #pragma unroll
            for (int mb = 0; mb < 2; ++mb)
                #pragma unroll
                for (int nb = 0; nb < 4; ++nb) {
                    mma_bf16(acc[mb][nb * 2],     ra[mb], rb[nb][0], rb[nb][2]);
                    mma_bf16(acc[mb][nb * 2 + 1], ra[mb], rb[nb][1], rb[nb][3]);
                }
        }
    };

    const int NG = npairs * KCPP;
    load_stage(0, 0);
    if (NG > 1) load_stage(1, 1);
    for (int g = 0; g < NG; ++g) {
        if (g == NG - 1)
            asm volatile("cp.async.wait_group 0;" ::: "memory");
        else
            asm volatile("cp.async.wait_group 1;" ::: "memory");
        __syncthreads();
        compute_stage(g % MMA_STAGES);
        __syncthreads();
        if (g + 2 < NG) load_stage(g + 2, (g + 2) % MMA_STAGES);
    }

    // ---- epilogue ----
    #pragma unroll
    for (int mb = 0; mb < 2; ++mb)
        #pragma unroll
        for (int nb = 0; nb < 8; ++nb) {
            const int gn = bn + wn + nb * 8 + (lane & 3) * 2;
            #pragma unroll
            for (int h = 0; h < 2; ++h) {
                const int gm = bm + wm + mb * 16 + (lane >> 2) + h * 8;
                if (gm < M) {
                    float vx = acc[mb][nb][h * 2];
                    float vy = acc[mb][nb][h * 2 + 1];
                    const float* ap = ADDM
                        ? add_or_bias + (long)gm * 512 + gn
                        : add_or_bias + gn;
                    const float2 av = *(const float2*)ap;
                    vx += av.x; vy += av.y;
                    if (SPLIT) {
                        __nv_bfloat162 lo2;
                        const __nv_bfloat162 hi2 = split_hi2(vx, vy, lo2);
                        *(__nv_bfloat162*)&Chi[(long)gm * 512 + gn] = hi2;
                        *(__nv_bfloat162*)&Clo[(long)gm * 512 + gn] = lo2;
                    } else {
                        *(float2*)&C[(long)gm * 512 + gn] = make_float2(vx, vy);
                    }
                }
            }
        }
}

// ======================= small kernels ======================================
// gather-sum over masked neighbors, reading hi/lo features, writing hi/lo sum
__global__ void gather_split_kernel(const __nv_bfloat16* __restrict__ Ahi,
                                    const __nv_bfloat16* __restrict__ Alo,
                                    const int* __restrict__ aidx,
                                    const int* __restrict__ num_nbs,
                                    __nv_bfloat16* __restrict__ Ghi,
                                    __nv_bfloat16* __restrict__ Glo) {
    const int node = blockIdx.x;               // 0..MN-1
    const int base = (node / NDIM) * NDIM;     // batch row offset
    const int e0 = threadIdx.x * 4;            // 128 threads x 4 elems
    const int nn = num_nbs[node];
    float s0 = 0.f, s1 = 0.f, s2 = 0.f, s3 = 0.f;
    #pragma unroll
    for (int k = 0; k < KNEI; ++k) {
        if (k >= nn) break;
        const int idx = __ldg(&aidx[((long)node * KNEI + k) * 2]);
        const long ro = (long)(base + idx) * HDIM + e0;
        const __nv_bfloat162 h0 = *(const __nv_bfloat162*)&Ahi[ro];
        const __nv_bfloat162 h1 = *(const __nv_bfloat162*)&Ahi[ro + 2];
        const __nv_bfloat162 l0 = *(const __nv_bfloat162*)&Alo[ro];
        const __nv_bfloat162 l1 = *(const __nv_bfloat162*)&Alo[ro + 2];
        s0 += __low2float(h0)  + __low2float(l0);
        s1 += __high2float(h0) + __high2float(l0);
        s2 += __low2float(h1)  + __low2float(l1);
        s3 += __high2float(h1) + __high2float(l1);
    }
    const long wo = (long)node * HDIM + e0;
    __nv_bfloat162 lo2a, lo2b;
    const __nv_bfloat162 hi2a = split_hi2(s0, s1, lo2a);
    const __nv_bfloat162 hi2b = split_hi2(s2, s3, lo2b);
    *(__nv_bfloat162*)&Ghi[wo]     = hi2a;
    *(__nv_bfloat162*)&Ghi[wo + 2] = hi2b;
    *(__nv_bfloat162*)&Glo[wo]     = lo2a;
    *(__nv_bfloat162*)&Glo[wo + 2] = lo2b;
}

// bond path: bondc[node,h] -> bf16 hi/lo directly
__global__ void bond_kernel(const float* __restrict__ input_bond,
                            const int* __restrict__ bidx,
                            const int* __restrict__ num_nbs,
                            const float* __restrict__ W_U2,
                            const float* __restrict__ b_U2,
                            __nv_bfloat16* __restrict__ BChi,
                            __nv_bfloat16* __restrict__ BClo) {
    const int node = blockIdx.x;
    const int b = node / NDIM;
    __shared__ float sbond[FB];
    __shared__ float scnt;
    const int tid = threadIdx.x;               // 128 threads
    if (tid < FB) {
        const int nn = num_nbs[node];
        float s = 0.f;
        for (int k = 0; k < nn; ++k) {
            int idx = __ldg(&bidx[((long)node * KNEI + k) * 2]);
            s += __ldg(&input_bond[((long)b * NDIM + idx) * FB + tid]);
        }
        sbond[tid] = s;
        if (tid == 0) scnt = (float)num_nbs[node];
    }
    __syncthreads();
    const float c = scnt;
    #pragma unroll
    for (int rep = 0; rep < HDIM / 256; ++rep) {
        const int h = tid * 2 + rep * 256;
        float vx = c * __ldg(&b_U2[h]);
        float vy = c * __ldg(&b_U2[h + 1]);
        #pragma unroll
        for (int f = 0; f < FB; ++f) {
            vx += sbond[f] * __ldg(&W_U2[(long)h * LDU2 + HDIM + f]);
            vy += sbond[f] * __ldg(&W_U2[(long)(h + 1) * LDU2 + HDIM + f]);
        }
        __nv_bfloat162 lo2;
        const __nv_bfloat162 hi2 = split_hi2(vx, vy, lo2);
        *(__nv_bfloat162*)&BChi[(long)node * HDIM + h] = hi2;
        *(__nv_bfloat162*)&BClo[(long)node * HDIM + h] = lo2;
    }
}

// transpose W_U2[:, 0:512] (ld=517) -> Wt[512][512]
__global__ void transpose_kernel(const float* __restrict__ W,
                                 float* __restrict__ T) {
    __shared__ float t[32][33];
    const int bx = blockIdx.x * 32, by = blockIdx.y * 32;
    const int x = threadIdx.x, y = threadIdx.y;    // 32 x 8
    #pragma unroll
    for (int i = 0; i < 32; i += 8)
        t[y + i][x] = __ldg(&W[(long)(by + y + i) * LDU2 + bx + x]);
    __syncthreads();
    #pragma unroll
    for (int i = 0; i < 32; i += 8)
        T[(long)(bx + y + i) * HDIM + by + x] = t[x][y + i];
}

// hi/lo bf16 split, contiguous fp32 input
__global__ void split_kernel(const float* __restrict__ x,
                             __nv_bfloat16* __restrict__ hi,
                             __nv_bfloat16* __restrict__ lo, int n4) {
    const int i = blockIdx.x * blockDim.x + threadIdx.x;
    if (i >= n4) return;
    const float4 v = ((const float4*)x)[i];
    __nv_bfloat162 lo2a, lo2b;
    const __nv_bfloat162 hi2a = split_hi2(v.x, v.y, lo2a);
    const __nv_bfloat162 hi2b = split_hi2(v.z, v.w, lo2b);
    ((__nv_bfloat162*)hi)[2 * i]     = hi2a;
    ((__nv_bfloat162*)hi)[2 * i + 1] = hi2b;
    ((__nv_bfloat162*)lo)[2 * i]     = lo2a;
    ((__nv_bfloat162*)lo)[2 * i + 1] = lo2b;
}

// strided weight split: out[n*512 + k] = W[n*ldw + koff + k]
__global__ void split_w_kernel(const float* __restrict__ W, int ldw, int koff,
                               __nv_bfloat16* __restrict__ hi,
                               __nv_bfloat16* __restrict__ lo) {
    const int idx = blockIdx.x * blockDim.x + threadIdx.x;
    if (idx >= HDIM * HDIM) return;
    const int n = idx >> 9, k = idx & 511;
    const float v = __ldg(&W[(long)n * ldw + koff + k]);
    const __nv_bfloat16 h = __float2bfloat16_rn(v);
    hi[idx] = h;
    lo[idx] = __float2bfloat16_rn(v - __bfloat162float(h));
}

// zero-padded split: [rows, cols] fp32 -> [rows, 128] bf16 hi/lo
__global__ void split_pad_kernel(const float* __restrict__ X, int rows, int cols,
                                 __nv_bfloat16* __restrict__ hi,
                                 __nv_bfloat16* __restrict__ lo) {
    const int idx = blockIdx.x * blockDim.x + threadIdx.x;
    if (idx >= rows * FAP) return;
    const int r = idx >> 7, c = idx & 127;
    const float v = (c < cols) ? __ldg(&X[(long)r * cols + c]) : 0.f;
    const __nv_bfloat16 h = __float2bfloat16_rn(v);
    hi[idx] = h;
    lo[idx] = __float2bfloat16_rn(v - __bfloat162float(h));
}

// ======================= host ===============================================
extern "C" void kernel_launch(void* const* d_in, const int* in_sizes, int n_in,
                              void* d_out, int out_size) {
    const float* input_atom = (const float*)d_in[0];
    const float* input_bond = (const float*)d_in[1];
    const int*   atom_nei   = (const int*)d_in[2];
    const int*   bond_nei   = (const int*)d_in[3];
    const int*   num_nbs    = (const int*)d_in[4];
    const float* W_atom     = (const float*)d_in[5];
    const float* W_U2       = (const float*)d_in[6];
    const float* b_U2       = (const float*)d_in[7];
    const float* W_U1       = (const float*)d_in[8];
    const float* b_U1       = (const float*)d_in[9];
    float* out = (float*)d_out;

    float *CONSTm, *Wt, *zero512;
    cudaGetSymbolAddress((void**)&CONSTm, g_CONST);
    cudaGetSymbolAddress((void**)&Wt, g_Wt);
    cudaGetSymbolAddress((void**)&zero512, g_zero512);
    __nv_bfloat16 *Ahi0, *Alo0, *Ahi1, *Alo1, *GGhi, *GGlo, *BChi, *BClo;
    __nv_bfloat16 *Wahi, *Walo, *Wbhi, *Wblo, *Wfhi, *Wflo, *Wthi, *Wtlo;
    __nv_bfloat16 *Pahi, *Palo, *PWhi, *PWlo;
    cudaGetSymbolAddress((void**)&Ahi0, g_Ahi0); cudaGetSymbolAddress((void**)&Alo0, g_Alo0);
    cudaGetSymbolAddress((void**)&Ahi1, g_Ahi1); cudaGetSymbolAddress((void**)&Alo1, g_Alo1);
    cudaGetSymbolAddress((void**)&GGhi, g_GGhi); cudaGetSymbolAddress((void**)&GGlo, g_GGlo);
    cudaGetSymbolAddress((void**)&BChi, g_BChi); cudaGetSymbolAddress((void**)&BClo, g_BClo);
    cudaGetSymbolAddress((void**)&Wahi, g_Wahi); cudaGetSymbolAddress((void**)&Walo, g_Walo);
    cudaGetSymbolAddress((void**)&Wbhi, g_Wbhi); cudaGetSymbolAddress((void**)&Wblo, g_Wblo);
    cudaGetSymbolAddress((void**)&Wfhi, g_Wfhi); cudaGetSymbolAddress((void**)&Wflo, g_Wflo);
    cudaGetSymbolAddress((void**)&Wthi, g_Wthi); cudaGetSymbolAddress((void**)&Wtlo, g_Wtlo);
    cudaGetSymbolAddress((void**)&Pahi, g_Pahi); cudaGetSymbolAddress((void**)&Palo, g_Palo);
    cudaGetSymbolAddress((void**)&PWhi, g_PWhi); cudaGetSymbolAddress((void**)&PWlo, g_PWlo);

    cudaFuncSetAttribute((const void*)mma_gemm<8, 512, true, true>,
                         cudaFuncAttributeMaxDynamicSharedMemorySize, SMEM_MMA);
    cudaFuncSetAttribute((const void*)mma_gemm<8, 512, true, false>,
                         cudaFuncAttributeMaxDynamicSharedMemorySize, SMEM_MMA);
    cudaFuncSetAttribute((const void*)mma_gemm<8, 512, false, false>,
                         cudaFuncAttributeMaxDynamicSharedMemorySize, SMEM_MMA);
    cudaFuncSetAttribute((const void*)mma_gemm<8, 512, false, true>,
                         cudaFuncAttributeMaxDynamicSharedMemorySize, SMEM_MMA);
    cudaFuncSetAttribute((const void*)mma_gemm<2, 128, false, true>,
                         cudaFuncAttributeMaxDynamicSharedMemorySize, SMEM_MMA);

    const dim3 thr(256);
    const dim3 grid_main(HDIM / 128, (MN + 127) / 128);   // 4 x 90
    const dim3 grid_sq(HDIM / 128, HDIM / 128);           // 4 x 4
    const int wblocks = (HDIM * HDIM + 255) / 256;

    // 1. Pad+split embed operands, then A0(hi/lo) = input_atom @ W_atom^T (bf16x3)
    split_pad_kernel<<<(MN * FAP + 255) / 256, 256>>>(input_atom, MN, FA, Pahi, Palo);
    split_pad_kernel<<<(HDIM * FAP + 255) / 256, 256>>>(W_atom, HDIM, FA, PWhi, PWlo);
    {
        GemmArgs p{};
        p.a[0] = Pahi; p.a[1] = Palo; p.a[2] = Pahi;
        p.b[0] = PWhi; p.b[1] = PWhi; p.b[2] = PWlo;
        mma_gemm<2, 128, false, true><<<grid_main, thr, SMEM_MMA>>>(
            p, 3, nullptr, Ahi0, Alo0, zero512, MN);
    }

    // 2. Bond precompute -> BChi/BClo (split fused)
    bond_kernel<<<MN, 128>>>(input_bond, bond_nei, num_nbs, W_U2, b_U2, BChi, BClo);

    // 3. Transpose W_U2a; split weight operands
    transpose_kernel<<<dim3(16, 16), dim3(32, 8)>>>(W_U2, Wt);
    split_w_kernel<<<wblocks, 256>>>(W_U1, LDU1, 0, Wahi, Walo);
    split_w_kernel<<<wblocks, 256>>>(W_U1, LDU1, HDIM, Wbhi, Wblo);
    split_kernel<<<(HDIM * HDIM / 4 + 255) / 256, 256>>>(Wt, Wthi, Wtlo,
                                                         HDIM * HDIM / 4);

    // 4. Fold: Wf(hi/lo) = W_U1b @ W_U2a  (bf16x3, split epilogue)
    {
        GemmArgs p{};
        p.a[0] = Wbhi; p.a[1] = Wblo; p.a[2] = Wbhi;
        p.b[0] = Wthi; p.b[1] = Wthi; p.b[2] = Wtlo;
        mma_gemm<8, 512, false, true><<<grid_sq, thr, SMEM_MMA>>>(
            p, 3, nullptr, Wfhi, Wflo, zero512, HDIM);
    }

    // 5. CONST = bondc @ W_U1b^T + b_U1  (fp32 output)
    {
        GemmArgs p{};
        p.a[0] = BChi; p.a[1] = BClo; p.a[2] = BChi;
        p.b[0] = Wbhi; p.b[1] = Wbhi; p.b[2] = Wblo;
        mma_gemm<8, 512, false, false><<<grid_main, thr, SMEM_MMA>>>(
            p, 3, CONSTm, nullptr, nullptr, b_U1, MN);
    }

    // 6. depth iterations: GG = gather(A); A' = A@W_U1a^T + GG@Wf^T + CONST
    __nv_bfloat16* srcHi = Ahi0;
    __nv_bfloat16* srcLo = Alo0;
    for (int d = 0; d < DEPTH; ++d) {
        gather_split_kernel<<<MN, 128>>>(srcHi, srcLo, atom_nei, num_nbs,
                                         GGhi, GGlo);
        GemmArgs p{};
        p.a[0] = srcHi; p.a[1] = srcLo; p.a[2] = srcHi;
        p.b[0] = Wahi;  p.b[1] = Wahi;  p.b[2] = Walo;
        p.a[3] = GGhi;  p.a[4] = GGlo;  p.a[5] = GGhi;
        p.b[3] = Wfhi;  p.b[4] = Wfhi;  p.b[5] = Wflo;
        if (d == DEPTH - 1) {
            mma_gemm<8, 512, true, false><<<grid_main, thr, SMEM_MMA>>>(
                p, 6, out, nullptr, nullptr, CONSTm, MN);
        } else {
            __nv_bfloat16* dstHi = (srcHi == Ahi0) ? Ahi1 : Ahi0;
            __nv_bfloat16* dstLo = (srcLo == Alo0) ? Alo1 : Alo0;
            mma_gemm<8, 512, true, true><<<grid_main, thr, SMEM_MMA>>>(
                p, 6, nullptr, dstHi, dstLo, CONSTm, MN);
            srcHi = dstHi; srcLo = dstLo;
        }
    }
}